// round 1
// baseline (speedup 1.0000x reference)
#include <cuda_runtime.h>
#include <cstdint>

// Problem constants
#define B_  2
#define S_  2048
#define H_  1024
#define NH_ 16
#define HD_ 64
#define M_  (B_*S_)   // 4096 rows for all projections

// Scratch (allocation-free: device globals)
__device__ float g_Q[(size_t)M_ * H_];
__device__ float g_K[(size_t)M_ * H_];
__device__ float g_V[(size_t)M_ * H_];
__device__ float g_C[(size_t)M_ * H_];

// ---------------------------------------------------------------------------
// fp32 GEMM: C[M_,H_] = A[M_,H_] @ W[H_,H_]
// 128x128 tile, BK=16, 256 threads, 8x8 per-thread microtile.
// ---------------------------------------------------------------------------
#define BM 128
#define BN 128
#define BK 16

__global__ __launch_bounds__(256, 2)
void gemm_f32(const float* __restrict__ A, const float* __restrict__ W,
              float* __restrict__ C) {
    const int N = H_, K = H_;
    __shared__ float As[BK][BM];   // transposed A tile
    __shared__ float Bs[BK][BN];

    const int tid = threadIdx.x;
    const int tx = tid & 15;       // 0..15 -> col group
    const int ty = tid >> 4;       // 0..15 -> row group
    const int row0 = blockIdx.y * BM;
    const int col0 = blockIdx.x * BN;

    float acc[8][8];
    #pragma unroll
    for (int i = 0; i < 8; i++)
        #pragma unroll
        for (int j = 0; j < 8; j++) acc[i][j] = 0.f;

    for (int k0 = 0; k0 < K; k0 += BK) {
        // Load A tile (128x16) -> As[k][m] (transposed)
        #pragma unroll
        for (int i = 0; i < 2; i++) {
            int lin = (tid + i * 256) * 4;
            int r = lin >> 4;          // 0..127
            int c = lin & 15;          // 0,4,8,12
            float4 v = *(const float4*)(A + (size_t)(row0 + r) * K + k0 + c);
            As[c + 0][r] = v.x;
            As[c + 1][r] = v.y;
            As[c + 2][r] = v.z;
            As[c + 3][r] = v.w;
        }
        // Load W tile (16x128) -> Bs[k][n]
        #pragma unroll
        for (int i = 0; i < 2; i++) {
            int lin = (tid + i * 256) * 4;
            int r = lin >> 7;          // 0..15
            int c = lin & 127;
            *(float4*)(&Bs[r][c]) =
                *(const float4*)(W + (size_t)(k0 + r) * N + col0 + c);
        }
        __syncthreads();

        #pragma unroll
        for (int kk = 0; kk < BK; kk++) {
            float a[8], b[8];
            *(float4*)(a)     = *(const float4*)(&As[kk][ty * 8]);
            *(float4*)(a + 4) = *(const float4*)(&As[kk][ty * 8 + 4]);
            *(float4*)(b)     = *(const float4*)(&Bs[kk][tx * 8]);
            *(float4*)(b + 4) = *(const float4*)(&Bs[kk][tx * 8 + 4]);
            #pragma unroll
            for (int i = 0; i < 8; i++)
                #pragma unroll
                for (int j = 0; j < 8; j++)
                    acc[i][j] += a[i] * b[j];
        }
        __syncthreads();
    }

    // Write back 8x8 microtile
    #pragma unroll
    for (int i = 0; i < 8; i++) {
        float* crow = C + (size_t)(row0 + ty * 8 + i) * N + col0 + tx * 8;
        *(float4*)(crow)     = make_float4(acc[i][0], acc[i][1], acc[i][2], acc[i][3]);
        *(float4*)(crow + 4) = make_float4(acc[i][4], acc[i][5], acc[i][6], acc[i][7]);
    }
}

// ---------------------------------------------------------------------------
// Flash attention (fp32): 1 thread = 1 query row. K/V tiles of 32 rows in smem.
// Matches reference: scores = clip(QK^T * scale, +-10000); mask==0 -> -inf;
// softmax; @V.
// ---------------------------------------------------------------------------
__global__ __launch_bounds__(128, 2)
void flash_attn_f32(const float* __restrict__ Q, const float* __restrict__ Kb,
                    const float* __restrict__ Vb, const int* __restrict__ mask,
                    float* __restrict__ Ctx) {
    const float NEG_INF = __int_as_float(0xff800000u);
    const float scale = 0.125f;   // HD^-0.5 = 1/8

    const int tid = threadIdx.x;
    const int qrow = blockIdx.x * 128 + tid;
    const int h = blockIdx.y;
    const int b = blockIdx.z;

    __shared__ float Ks[32][HD_];
    __shared__ float Vs[32][HD_];
    __shared__ int   mk[32];

    // Load this thread's Q row into registers
    float qr[HD_];
    {
        const float4* qp = (const float4*)(Q + ((size_t)(b * S_ + qrow) * H_ + h * HD_));
        #pragma unroll
        for (int i = 0; i < HD_ / 4; i++) ((float4*)qr)[i] = qp[i];
    }

    float o[HD_];
    #pragma unroll
    for (int d = 0; d < HD_; d++) o[d] = 0.f;
    float mrow = NEG_INF, l = 0.f;

    for (int kv0 = 0; kv0 < S_; kv0 += 32) {
        // Cooperative load of K/V tiles (32 x 64 each)
        #pragma unroll
        for (int i = 0; i < 4; i++) {
            int lin = (tid + i * 128) * 4;
            int r = lin >> 6;      // 0..31
            int c = lin & 63;
            size_t goff = (size_t)(b * S_ + kv0 + r) * H_ + h * HD_ + c;
            *(float4*)(&Ks[r][c]) = *(const float4*)(Kb + goff);
            *(float4*)(&Vs[r][c]) = *(const float4*)(Vb + goff);
        }
        if (tid < 32) mk[tid] = mask[b * S_ + kv0 + tid];
        __syncthreads();

        // Scores for 32 keys
        float s[32];
        float mt = NEG_INF;
        #pragma unroll
        for (int j = 0; j < 32; j++) {
            float a0 = 0.f, a1 = 0.f, a2 = 0.f, a3 = 0.f;
            #pragma unroll
            for (int d4 = 0; d4 < HD_ / 4; d4++) {
                float4 kv = *(const float4*)(&Ks[j][d4 * 4]);
                a0 += qr[d4 * 4 + 0] * kv.x;
                a1 += qr[d4 * 4 + 1] * kv.y;
                a2 += qr[d4 * 4 + 2] * kv.z;
                a3 += qr[d4 * 4 + 3] * kv.w;
            }
            float v = ((a0 + a1) + (a2 + a3)) * scale;
            v = fminf(fmaxf(v, -10000.f), 10000.f);   // clip BEFORE mask
            if (mk[j] == 0) v = NEG_INF;
            s[j] = v;
            mt = fmaxf(mt, v);
        }

        float mnew = fmaxf(mrow, mt);
        if (mnew != NEG_INF) {   // skip fully-masked tile (keeps state NaN-free)
            float alpha = __expf(mrow - mnew);   // exp(-inf) = 0 on first tile
            l *= alpha;
            #pragma unroll
            for (int d = 0; d < HD_; d++) o[d] *= alpha;
            #pragma unroll
            for (int j = 0; j < 32; j++) {
                float p = __expf(s[j] - mnew);
                l += p;
                #pragma unroll
                for (int d4 = 0; d4 < HD_ / 4; d4++) {
                    float4 vv = *(const float4*)(&Vs[j][d4 * 4]);
                    o[d4 * 4 + 0] += p * vv.x;
                    o[d4 * 4 + 1] += p * vv.y;
                    o[d4 * 4 + 2] += p * vv.z;
                    o[d4 * 4 + 3] += p * vv.w;
                }
            }
            mrow = mnew;
        }
        __syncthreads();
    }

    const float inv = 1.f / l;
    float* op = Ctx + ((size_t)(b * S_ + qrow) * H_ + h * HD_);
    #pragma unroll
    for (int d4 = 0; d4 < HD_ / 4; d4++) {
        float4 v = make_float4(o[d4 * 4 + 0] * inv, o[d4 * 4 + 1] * inv,
                               o[d4 * 4 + 2] * inv, o[d4 * 4 + 3] * inv);
        ((float4*)op)[d4] = v;
    }
}

// ---------------------------------------------------------------------------
// Launch
// ---------------------------------------------------------------------------
extern "C" void kernel_launch(void* const* d_in, const int* in_sizes, int n_in,
                              void* d_out, int out_size) {
    const float* X    = (const float*)d_in[0];
    const int*   mask = (const int*)d_in[1];
    const float* WQ   = (const float*)d_in[2];
    const float* WK   = (const float*)d_in[3];
    const float* WV   = (const float*)d_in[4];
    const float* WO   = (const float*)d_in[5];
    float* out = (float*)d_out;

    float *Qd, *Kd, *Vd, *Cd;
    cudaGetSymbolAddress((void**)&Qd, g_Q);
    cudaGetSymbolAddress((void**)&Kd, g_K);
    cudaGetSymbolAddress((void**)&Vd, g_V);
    cudaGetSymbolAddress((void**)&Cd, g_C);

    dim3 gblk(256);
    dim3 ggrd(H_ / BN, M_ / BM);     // (8, 32)
    gemm_f32<<<ggrd, gblk>>>(X, WQ, Qd);
    gemm_f32<<<ggrd, gblk>>>(X, WK, Kd);
    gemm_f32<<<ggrd, gblk>>>(X, WV, Vd);

    dim3 fblk(128);
    dim3 fgrd(S_ / 128, NH_, B_);    // (16, 16, 2)
    flash_attn_f32<<<fgrd, fblk>>>(Qd, Kd, Vd, mask, Cd);

    gemm_f32<<<ggrd, gblk>>>(Cd, WO, out);
}

// round 3
// speedup vs baseline: 1.1963x; 1.1963x over previous
#include <cuda_runtime.h>
#include <cuda_bf16.h>
#include <cstdint>

// Problem constants
#define B_  2
#define S_  2048
#define H_  1024
#define NH_ 16
#define HD_ 64
#define M_  (B_*S_)   // 4096 rows for all projections

// ---------------------------------------------------------------------------
// Scratch (allocation-free: device globals)
// ---------------------------------------------------------------------------
__device__ float g_Q[(size_t)M_ * H_];
__device__ float g_K[(size_t)M_ * H_];
__device__ float g_V[(size_t)M_ * H_];
__device__ float g_C[(size_t)M_ * H_];
__device__ __nv_bfloat16 g_Xh[(size_t)M_ * H_];
__device__ __nv_bfloat16 g_Xl[(size_t)M_ * H_];
__device__ __nv_bfloat16 g_Wh[4][(size_t)H_ * H_];   // transposed [N,K] high
__device__ __nv_bfloat16 g_Wl[4][(size_t)H_ * H_];   // transposed [N,K] low

// ---------------------------------------------------------------------------
// Helpers
// ---------------------------------------------------------------------------
__device__ __forceinline__ uint32_t smem_u32(const void* p) {
    uint32_t a;
    asm("{ .reg .u64 t; cvta.to.shared.u64 t, %1; cvt.u32.u64 %0, t; }"
        : "=r"(a) : "l"(p));
    return a;
}
__device__ __forceinline__ void cp16(uint32_t s, const void* g) {
    asm volatile("cp.async.cg.shared.global [%0], [%1], 16;" :: "r"(s), "l"(g));
}
__device__ __forceinline__ void mma16816(float* c, const uint32_t* a, const uint32_t* b) {
    asm volatile(
        "mma.sync.aligned.m16n8k16.row.col.f32.bf16.bf16.f32 "
        "{%0,%1,%2,%3}, {%4,%5,%6,%7}, {%8,%9}, {%0,%1,%2,%3};"
        : "+f"(c[0]), "+f"(c[1]), "+f"(c[2]), "+f"(c[3])
        : "r"(a[0]), "r"(a[1]), "r"(a[2]), "r"(a[3]), "r"(b[0]), "r"(b[1]));
}

// ---------------------------------------------------------------------------
// bf16 split-3 GEMM via mma.sync:  C[M_,H_] = Ah@BhT^T + Al@BhT^T + Ah@BlT^T
// (BT stored [N,K] row-major, K contiguous -> mma "col" operand)
// CTA tile 128x128, BK=32, 8 warps (2x4), warp tile 64x32. cp.async 2-stage.
// ---------------------------------------------------------------------------
#define TM 128
#define TN 128
#define TK 32
#define PITCH 40                 // bf16 per smem row (80 B) -> conflict-free frags
#define NCHUNK (3 * H_ / TK)     // 96

__global__ __launch_bounds__(256, 2)
void gemm_mma(const __nv_bfloat16* __restrict__ Ah, const __nv_bfloat16* __restrict__ Al,
              const __nv_bfloat16* __restrict__ BhT, const __nv_bfloat16* __restrict__ BlT,
              float* __restrict__ C) {
    __shared__ __nv_bfloat16 As[2][TM * PITCH];
    __shared__ __nv_bfloat16 Bs[2][TN * PITCH];

    const int tid = threadIdx.x;
    const int wid = tid >> 5;
    const int lane = tid & 31;
    const int gid = lane >> 2;       // 0..7
    const int t = lane & 3;          // 0..3
    const int wm = wid & 1;          // M dir (2 warps)
    const int wn = wid >> 1;         // N dir (4 warps)
    const int row0 = blockIdx.y * TM;
    const int col0 = blockIdx.x * TN;

    const uint32_t sA0 = smem_u32(&As[0][0]);
    const uint32_t sA1 = smem_u32(&As[1][0]);
    const uint32_t sB0 = smem_u32(&Bs[0][0]);
    const uint32_t sB1 = smem_u32(&Bs[1][0]);

    float acc[4][4][4];
    #pragma unroll
    for (int i = 0; i < 4; i++)
        #pragma unroll
        for (int j = 0; j < 4; j++)
            #pragma unroll
            for (int q = 0; q < 4; q++) acc[i][j][q] = 0.f;

    // chunk c: pair p = c/32 selects (Ah,Bh),(Al,Bh),(Ah,Bl); k0 = (c%32)*TK
    auto load_chunk = [&](int c, int buf) {
        const int p = c >> 5;
        const int k0 = (c & 31) * TK;
        const __nv_bfloat16* Ap = (p == 1) ? Al : Ah;
        const __nv_bfloat16* Bp = (p == 2) ? BlT : BhT;
        const uint32_t sa = buf ? sA1 : sA0;
        const uint32_t sb = buf ? sB1 : sB0;
        #pragma unroll
        for (int i = 0; i < 2; i++) {
            int idx = tid + i * 256;          // 0..511
            int r = idx >> 2, c16 = idx & 3;  // row, 16B chunk
            cp16(sa + r * 80 + c16 * 16, Ap + (size_t)(row0 + r) * H_ + k0 + c16 * 8);
            cp16(sb + r * 80 + c16 * 16, Bp + (size_t)(col0 + r) * H_ + k0 + c16 * 8);
        }
        asm volatile("cp.async.commit_group;" ::: "memory");
    };

    load_chunk(0, 0);

    for (int c = 0; c < NCHUNK; c++) {
        const int buf = c & 1;
        if (c + 1 < NCHUNK) {
            load_chunk(c + 1, buf ^ 1);
            asm volatile("cp.async.wait_group 1;" ::: "memory");
        } else {
            asm volatile("cp.async.wait_group 0;" ::: "memory");
        }
        __syncthreads();

        const __nv_bfloat16* Ab = &As[buf][0];
        const __nv_bfloat16* Bb = &Bs[buf][0];

        #pragma unroll
        for (int ks = 0; ks < 2; ks++) {
            const int kc = ks * 16 + 2 * t;
            uint32_t a[4][4], b[4][2];
            #pragma unroll
            for (int mt = 0; mt < 4; mt++) {
                const int r0 = wm * 64 + mt * 16 + gid;
                a[mt][0] = *(const uint32_t*)(Ab + r0 * PITCH + kc);
                a[mt][1] = *(const uint32_t*)(Ab + (r0 + 8) * PITCH + kc);
                a[mt][2] = *(const uint32_t*)(Ab + r0 * PITCH + kc + 8);
                a[mt][3] = *(const uint32_t*)(Ab + (r0 + 8) * PITCH + kc + 8);
            }
            #pragma unroll
            for (int nt = 0; nt < 4; nt++) {
                const int n0 = wn * 32 + nt * 8 + gid;
                b[nt][0] = *(const uint32_t*)(Bb + n0 * PITCH + kc);
                b[nt][1] = *(const uint32_t*)(Bb + n0 * PITCH + kc + 8);
            }
            #pragma unroll
            for (int mt = 0; mt < 4; mt++)
                #pragma unroll
                for (int nt = 0; nt < 4; nt++)
                    mma16816(acc[mt][nt], a[mt], b[nt]);
        }
        __syncthreads();
    }

    // Epilogue: c0,c1 -> (row, col 2t..2t+1); c2,c3 -> (row+8, same cols)
    #pragma unroll
    for (int mt = 0; mt < 4; mt++) {
        const int rg = row0 + wm * 64 + mt * 16 + gid;
        #pragma unroll
        for (int nt = 0; nt < 4; nt++) {
            const int cg = col0 + wn * 32 + nt * 8 + 2 * t;
            *(float2*)(C + (size_t)rg * H_ + cg) =
                make_float2(acc[mt][nt][0], acc[mt][nt][1]);
            *(float2*)(C + (size_t)(rg + 8) * H_ + cg) =
                make_float2(acc[mt][nt][2], acc[mt][nt][3]);
        }
    }
}

// ---------------------------------------------------------------------------
// Split fp32 -> (bf16 hi, bf16 lo), vectorized by 4
// ---------------------------------------------------------------------------
__global__ void xsplit(const float* __restrict__ A, __nv_bfloat16* __restrict__ Ah,
                       __nv_bfloat16* __restrict__ Al, int n4) {
    int i = blockIdx.x * blockDim.x + threadIdx.x;
    if (i >= n4) return;
    float4 v = ((const float4*)A)[i];
    __nv_bfloat16 h0 = __float2bfloat16(v.x);
    __nv_bfloat16 h1 = __float2bfloat16(v.y);
    __nv_bfloat16 h2 = __float2bfloat16(v.z);
    __nv_bfloat16 h3 = __float2bfloat16(v.w);
    __nv_bfloat16 l0 = __float2bfloat16(v.x - __bfloat162float(h0));
    __nv_bfloat16 l1 = __float2bfloat16(v.y - __bfloat162float(h1));
    __nv_bfloat16 l2 = __float2bfloat16(v.z - __bfloat162float(h2));
    __nv_bfloat16 l3 = __float2bfloat16(v.w - __bfloat162float(h3));
    ((__nv_bfloat162*)Ah)[2 * i + 0] = __nv_bfloat162(h0, h1);
    ((__nv_bfloat162*)Ah)[2 * i + 1] = __nv_bfloat162(h2, h3);
    ((__nv_bfloat162*)Al)[2 * i + 0] = __nv_bfloat162(l0, l1);
    ((__nv_bfloat162*)Al)[2 * i + 1] = __nv_bfloat162(l2, l3);
}

// ---------------------------------------------------------------------------
// Transpose + split weights: W[K,N] fp32 -> WhT/WlT[N,K] bf16
// ---------------------------------------------------------------------------
__global__ void wsplit_t(const float* __restrict__ W, __nv_bfloat16* __restrict__ WhT,
                         __nv_bfloat16* __restrict__ WlT) {
    __shared__ float tbuf[32][33];
    int n0 = blockIdx.x * 32, k0 = blockIdx.y * 32;
    int x = threadIdx.x, y0 = threadIdx.y;
    #pragma unroll
    for (int i = y0; i < 32; i += 8)
        tbuf[i][x] = W[(size_t)(k0 + i) * H_ + n0 + x];
    __syncthreads();
    #pragma unroll
    for (int i = y0; i < 32; i += 8) {
        float v = tbuf[x][i];
        __nv_bfloat16 h = __float2bfloat16(v);
        WhT[(size_t)(n0 + i) * H_ + k0 + x] = h;
        WlT[(size_t)(n0 + i) * H_ + k0 + x] = __float2bfloat16(v - __bfloat162float(h));
    }
}

// ---------------------------------------------------------------------------
// Flash attention (fp32, unchanged — round 1 verified)
// ---------------------------------------------------------------------------
__global__ __launch_bounds__(128, 2)
void flash_attn_f32(const float* __restrict__ Q, const float* __restrict__ Kb,
                    const float* __restrict__ Vb, const int* __restrict__ mask,
                    float* __restrict__ Ctx) {
    const float NEG_INF = __int_as_float(0xff800000u);
    const float scale = 0.125f;

    const int tid = threadIdx.x;
    const int qrow = blockIdx.x * 128 + tid;
    const int h = blockIdx.y;
    const int b = blockIdx.z;

    __shared__ float Ks[32][HD_];
    __shared__ float Vs[32][HD_];
    __shared__ int   mk[32];

    float qr[HD_];
    {
        const float4* qp = (const float4*)(Q + ((size_t)(b * S_ + qrow) * H_ + h * HD_));
        #pragma unroll
        for (int i = 0; i < HD_ / 4; i++) ((float4*)qr)[i] = qp[i];
    }

    float o[HD_];
    #pragma unroll
    for (int d = 0; d < HD_; d++) o[d] = 0.f;
    float mrow = NEG_INF, l = 0.f;

    for (int kv0 = 0; kv0 < S_; kv0 += 32) {
        #pragma unroll
        for (int i = 0; i < 4; i++) {
            int lin = (tid + i * 128) * 4;
            int r = lin >> 6;
            int c = lin & 63;
            size_t goff = (size_t)(b * S_ + kv0 + r) * H_ + h * HD_ + c;
            *(float4*)(&Ks[r][c]) = *(const float4*)(Kb + goff);
            *(float4*)(&Vs[r][c]) = *(const float4*)(Vb + goff);
        }
        if (tid < 32) mk[tid] = mask[b * S_ + kv0 + tid];
        __syncthreads();

        float s[32];
        float mt = NEG_INF;
        #pragma unroll
        for (int j = 0; j < 32; j++) {
            float a0 = 0.f, a1 = 0.f, a2 = 0.f, a3 = 0.f;
            #pragma unroll
            for (int d4 = 0; d4 < HD_ / 4; d4++) {
                float4 kv = *(const float4*)(&Ks[j][d4 * 4]);
                a0 += qr[d4 * 4 + 0] * kv.x;
                a1 += qr[d4 * 4 + 1] * kv.y;
                a2 += qr[d4 * 4 + 2] * kv.z;
                a3 += qr[d4 * 4 + 3] * kv.w;
            }
            float v = ((a0 + a1) + (a2 + a3)) * scale;
            v = fminf(fmaxf(v, -10000.f), 10000.f);
            if (mk[j] == 0) v = NEG_INF;
            s[j] = v;
            mt = fmaxf(mt, v);
        }

        float mnew = fmaxf(mrow, mt);
        if (mnew != NEG_INF) {
            float alpha = __expf(mrow - mnew);
            l *= alpha;
            #pragma unroll
            for (int d = 0; d < HD_; d++) o[d] *= alpha;
            #pragma unroll
            for (int j = 0; j < 32; j++) {
                float p = __expf(s[j] - mnew);
                l += p;
                #pragma unroll
                for (int d4 = 0; d4 < HD_ / 4; d4++) {
                    float4 vv = *(const float4*)(&Vs[j][d4 * 4]);
                    o[d4 * 4 + 0] += p * vv.x;
                    o[d4 * 4 + 1] += p * vv.y;
                    o[d4 * 4 + 2] += p * vv.z;
                    o[d4 * 4 + 3] += p * vv.w;
                }
            }
            mrow = mnew;
        }
        __syncthreads();
    }

    const float inv = 1.f / l;
    float* op = Ctx + ((size_t)(b * S_ + qrow) * H_ + h * HD_);
    #pragma unroll
    for (int d4 = 0; d4 < HD_ / 4; d4++) {
        float4 v = make_float4(o[d4 * 4 + 0] * inv, o[d4 * 4 + 1] * inv,
                               o[d4 * 4 + 2] * inv, o[d4 * 4 + 3] * inv);
        ((float4*)op)[d4] = v;
    }
}

// ---------------------------------------------------------------------------
// Launch
// ---------------------------------------------------------------------------
extern "C" void kernel_launch(void* const* d_in, const int* in_sizes, int n_in,
                              void* d_out, int out_size) {
    const float* X    = (const float*)d_in[0];
    const int*   mask = (const int*)d_in[1];
    const float* WQ   = (const float*)d_in[2];
    const float* WK   = (const float*)d_in[3];
    const float* WV   = (const float*)d_in[4];
    const float* WO   = (const float*)d_in[5];
    float* out = (float*)d_out;

    float *Qd, *Kd, *Vd, *Cd;
    __nv_bfloat16 *Xh, *Xl, *Wh, *Wl;
    cudaGetSymbolAddress((void**)&Qd, g_Q);
    cudaGetSymbolAddress((void**)&Kd, g_K);
    cudaGetSymbolAddress((void**)&Vd, g_V);
    cudaGetSymbolAddress((void**)&Cd, g_C);
    cudaGetSymbolAddress((void**)&Xh, g_Xh);
    cudaGetSymbolAddress((void**)&Xl, g_Xl);
    cudaGetSymbolAddress((void**)&Wh, g_Wh);
    cudaGetSymbolAddress((void**)&Wl, g_Wl);

    const size_t WSZ = (size_t)H_ * H_;

    // Prep: split X; transpose+split weights
    xsplit<<<(M_ * H_ / 4 + 255) / 256, 256>>>(X, Xh, Xl, M_ * H_ / 4);
    dim3 wgrd(32, 32), wblk(32, 8);
    wsplit_t<<<wgrd, wblk>>>(WQ, Wh + 0 * WSZ, Wl + 0 * WSZ);
    wsplit_t<<<wgrd, wblk>>>(WK, Wh + 1 * WSZ, Wl + 1 * WSZ);
    wsplit_t<<<wgrd, wblk>>>(WV, Wh + 2 * WSZ, Wl + 2 * WSZ);
    wsplit_t<<<wgrd, wblk>>>(WO, Wh + 3 * WSZ, Wl + 3 * WSZ);

    // Q/K/V projections on tensor cores (mma.sync bf16 split-3)
    dim3 ggrd(H_ / TN, M_ / TM);   // (8, 32)
    gemm_mma<<<ggrd, 256>>>(Xh, Xl, Wh + 0 * WSZ, Wl + 0 * WSZ, Qd);
    gemm_mma<<<ggrd, 256>>>(Xh, Xl, Wh + 1 * WSZ, Wl + 1 * WSZ, Kd);
    gemm_mma<<<ggrd, 256>>>(Xh, Xl, Wh + 2 * WSZ, Wl + 2 * WSZ, Vd);

    // Attention
    dim3 fblk(128);
    dim3 fgrd(S_ / 128, NH_, B_);
    flash_attn_f32<<<fgrd, fblk>>>(Qd, Kd, Vd, mask, Cd);

    // Output projection
    xsplit<<<(M_ * H_ / 4 + 255) / 256, 256>>>(Cd, Xh, Xl, M_ * H_ / 4);
    gemm_mma<<<ggrd, 256>>>(Xh, Xl, Wh + 3 * WSZ, Wl + 3 * WSZ, out);
}

// round 4
// speedup vs baseline: 2.3330x; 1.9501x over previous
#include <cuda_runtime.h>
#include <cuda_bf16.h>
#include <cstdint>

// Problem constants
#define B_  2
#define S_  2048
#define H_  1024
#define NH_ 16
#define HD_ 64
#define M_  (B_*S_)   // 4096 rows for all projections

// ---------------------------------------------------------------------------
// Scratch (allocation-free: device globals)
// ---------------------------------------------------------------------------
__device__ float g_Q[(size_t)M_ * H_];
__device__ float g_K[(size_t)M_ * H_];
__device__ float g_V[(size_t)M_ * H_];
__device__ __nv_bfloat16 g_Xh[(size_t)M_ * H_];
__device__ __nv_bfloat16 g_Xl[(size_t)M_ * H_];
__device__ __nv_bfloat16 g_Wh[4][(size_t)H_ * H_];   // transposed [N,K] high
__device__ __nv_bfloat16 g_Wl[4][(size_t)H_ * H_];   // transposed [N,K] low
// Per-head attention operands (bf16 split)
__device__ __nv_bfloat16 g_Qah[(size_t)M_ * H_];     // [b,h,s,d]
__device__ __nv_bfloat16 g_Qal[(size_t)M_ * H_];
__device__ __nv_bfloat16 g_Kah[(size_t)M_ * H_];     // [b,h,s,d]
__device__ __nv_bfloat16 g_Kal[(size_t)M_ * H_];
__device__ __nv_bfloat16 g_Vth[(size_t)M_ * H_];     // [b,h,d,s] (transposed)
__device__ __nv_bfloat16 g_Vtl[(size_t)M_ * H_];
__device__ __nv_bfloat16 g_Ch[(size_t)M_ * H_];      // context split [s,H]
__device__ __nv_bfloat16 g_Cl[(size_t)M_ * H_];

// ---------------------------------------------------------------------------
// Helpers
// ---------------------------------------------------------------------------
__device__ __forceinline__ uint32_t smem_u32(const void* p) {
    uint32_t a;
    asm("{ .reg .u64 t; cvta.to.shared.u64 t, %1; cvt.u32.u64 %0, t; }"
        : "=r"(a) : "l"(p));
    return a;
}
__device__ __forceinline__ void cp16(uint32_t s, const void* g) {
    asm volatile("cp.async.cg.shared.global [%0], [%1], 16;" :: "r"(s), "l"(g));
}
__device__ __forceinline__ void cp4(uint32_t s, const void* g) {
    asm volatile("cp.async.ca.shared.global [%0], [%1], 4;" :: "r"(s), "l"(g));
}
__device__ __forceinline__ void mma16816(float* c, const uint32_t* a, const uint32_t* b) {
    asm volatile(
        "mma.sync.aligned.m16n8k16.row.col.f32.bf16.bf16.f32 "
        "{%0,%1,%2,%3}, {%4,%5,%6,%7}, {%8,%9}, {%0,%1,%2,%3};"
        : "+f"(c[0]), "+f"(c[1]), "+f"(c[2]), "+f"(c[3])
        : "r"(a[0]), "r"(a[1]), "r"(a[2]), "r"(a[3]), "r"(b[0]), "r"(b[1]));
}
// pack two fp32 -> (bf16x2 hi, bf16x2 lo)
__device__ __forceinline__ void pack_split(float f0, float f1, uint32_t& hi, uint32_t& lo) {
    __nv_bfloat162 hh = __floats2bfloat162_rn(f0, f1);
    float r0 = f0 - __bfloat162float(hh.x);
    float r1 = f1 - __bfloat162float(hh.y);
    __nv_bfloat162 ll = __floats2bfloat162_rn(r0, r1);
    hi = *(uint32_t*)&hh;
    lo = *(uint32_t*)&ll;
}

// ---------------------------------------------------------------------------
// bf16 split-3 GEMM via mma.sync (unchanged from round 3 — verified)
// ---------------------------------------------------------------------------
#define TM 128
#define TN 128
#define TK 32
#define PITCH 40
#define NCHUNK (3 * H_ / TK)     // 96

__global__ __launch_bounds__(256, 2)
void gemm_mma(const __nv_bfloat16* __restrict__ Ah, const __nv_bfloat16* __restrict__ Al,
              const __nv_bfloat16* __restrict__ BhT, const __nv_bfloat16* __restrict__ BlT,
              float* __restrict__ C) {
    __shared__ __nv_bfloat16 As[2][TM * PITCH];
    __shared__ __nv_bfloat16 Bs[2][TN * PITCH];

    const int tid = threadIdx.x;
    const int wid = tid >> 5;
    const int lane = tid & 31;
    const int gid = lane >> 2;
    const int t = lane & 3;
    const int wm = wid & 1;
    const int wn = wid >> 1;
    const int row0 = blockIdx.y * TM;
    const int col0 = blockIdx.x * TN;

    const uint32_t sA0 = smem_u32(&As[0][0]);
    const uint32_t sA1 = smem_u32(&As[1][0]);
    const uint32_t sB0 = smem_u32(&Bs[0][0]);
    const uint32_t sB1 = smem_u32(&Bs[1][0]);

    float acc[4][4][4];
    #pragma unroll
    for (int i = 0; i < 4; i++)
        #pragma unroll
        for (int j = 0; j < 4; j++)
            #pragma unroll
            for (int q = 0; q < 4; q++) acc[i][j][q] = 0.f;

    auto load_chunk = [&](int c, int buf) {
        const int p = c >> 5;
        const int k0 = (c & 31) * TK;
        const __nv_bfloat16* Ap = (p == 1) ? Al : Ah;
        const __nv_bfloat16* Bp = (p == 2) ? BlT : BhT;
        const uint32_t sa = buf ? sA1 : sA0;
        const uint32_t sb = buf ? sB1 : sB0;
        #pragma unroll
        for (int i = 0; i < 2; i++) {
            int idx = tid + i * 256;
            int r = idx >> 2, c16 = idx & 3;
            cp16(sa + r * 80 + c16 * 16, Ap + (size_t)(row0 + r) * H_ + k0 + c16 * 8);
            cp16(sb + r * 80 + c16 * 16, Bp + (size_t)(col0 + r) * H_ + k0 + c16 * 8);
        }
        asm volatile("cp.async.commit_group;" ::: "memory");
    };

    load_chunk(0, 0);

    for (int c = 0; c < NCHUNK; c++) {
        const int buf = c & 1;
        if (c + 1 < NCHUNK) {
            load_chunk(c + 1, buf ^ 1);
            asm volatile("cp.async.wait_group 1;" ::: "memory");
        } else {
            asm volatile("cp.async.wait_group 0;" ::: "memory");
        }
        __syncthreads();

        const __nv_bfloat16* Ab = &As[buf][0];
        const __nv_bfloat16* Bb = &Bs[buf][0];

        #pragma unroll
        for (int ks = 0; ks < 2; ks++) {
            const int kc = ks * 16 + 2 * t;
            uint32_t a[4][4], b[4][2];
            #pragma unroll
            for (int mt = 0; mt < 4; mt++) {
                const int r0 = wm * 64 + mt * 16 + gid;
                a[mt][0] = *(const uint32_t*)(Ab + r0 * PITCH + kc);
                a[mt][1] = *(const uint32_t*)(Ab + (r0 + 8) * PITCH + kc);
                a[mt][2] = *(const uint32_t*)(Ab + r0 * PITCH + kc + 8);
                a[mt][3] = *(const uint32_t*)(Ab + (r0 + 8) * PITCH + kc + 8);
            }
            #pragma unroll
            for (int nt = 0; nt < 4; nt++) {
                const int n0 = wn * 32 + nt * 8 + gid;
                b[nt][0] = *(const uint32_t*)(Bb + n0 * PITCH + kc);
                b[nt][1] = *(const uint32_t*)(Bb + n0 * PITCH + kc + 8);
            }
            #pragma unroll
            for (int mt = 0; mt < 4; mt++)
                #pragma unroll
                for (int nt = 0; nt < 4; nt++)
                    mma16816(acc[mt][nt], a[mt], b[nt]);
        }
        __syncthreads();
    }

    #pragma unroll
    for (int mt = 0; mt < 4; mt++) {
        const int rg = row0 + wm * 64 + mt * 16 + gid;
        #pragma unroll
        for (int nt = 0; nt < 4; nt++) {
            const int cg = col0 + wn * 32 + nt * 8 + 2 * t;
            *(float2*)(C + (size_t)rg * H_ + cg) =
                make_float2(acc[mt][nt][0], acc[mt][nt][1]);
            *(float2*)(C + (size_t)(rg + 8) * H_ + cg) =
                make_float2(acc[mt][nt][2], acc[mt][nt][3]);
        }
    }
}

// ---------------------------------------------------------------------------
// Prep: fp32 Q/K/V -> per-head split bf16 (Q,K straight; V transposed)
// grid (S_/64, NH_, B_), 256 threads. Tile: 64 s-rows x 64 d.
// ---------------------------------------------------------------------------
__global__ __launch_bounds__(256)
void attn_prep(const float* __restrict__ Qf, const float* __restrict__ Kf,
               const float* __restrict__ Vf) {
    __shared__ float vt[64][65];
    const int tid = threadIdx.x;
    const int s0 = blockIdx.x * 64;
    const int h = blockIdx.y;
    const int b = blockIdx.z;
    const size_t bh = (size_t)b * NH_ + h;

    #pragma unroll
    for (int i = 0; i < 4; i++) {
        int idx = tid + i * 256;
        int r = idx >> 4;
        int c4 = (idx & 15) * 4;
        size_t gin = (size_t)(b * S_ + s0 + r) * H_ + h * HD_ + c4;
        size_t gout = (bh * S_ + s0 + r) * HD_ + c4;

        float4 q = *(const float4*)(Qf + gin);
        uint32_t qh0, ql0, qh1, ql1;
        pack_split(q.x, q.y, qh0, ql0);
        pack_split(q.z, q.w, qh1, ql1);
        *(uint32_t*)(g_Qah + gout) = qh0; *(uint32_t*)(g_Qah + gout + 2) = qh1;
        *(uint32_t*)(g_Qal + gout) = ql0; *(uint32_t*)(g_Qal + gout + 2) = ql1;

        float4 k = *(const float4*)(Kf + gin);
        pack_split(k.x, k.y, qh0, ql0);
        pack_split(k.z, k.w, qh1, ql1);
        *(uint32_t*)(g_Kah + gout) = qh0; *(uint32_t*)(g_Kah + gout + 2) = qh1;
        *(uint32_t*)(g_Kal + gout) = ql0; *(uint32_t*)(g_Kal + gout + 2) = ql1;

        float4 v = *(const float4*)(Vf + gin);
        vt[r][c4 + 0] = v.x; vt[r][c4 + 1] = v.y;
        vt[r][c4 + 2] = v.z; vt[r][c4 + 3] = v.w;
    }
    __syncthreads();
    #pragma unroll
    for (int i = 0; i < 4; i++) {
        int idx = tid + i * 256;
        int d = idx >> 4;
        int s4 = (idx & 15) * 4;
        float f0 = vt[s4 + 0][d], f1 = vt[s4 + 1][d];
        float f2 = vt[s4 + 2][d], f3 = vt[s4 + 3][d];
        uint32_t h0, l0, h1, l1;
        pack_split(f0, f1, h0, l0);
        pack_split(f2, f3, h1, l1);
        size_t gout = (bh * HD_ + d) * S_ + s0 + s4;
        *(uint32_t*)(g_Vth + gout) = h0; *(uint32_t*)(g_Vth + gout + 2) = h1;
        *(uint32_t*)(g_Vtl + gout) = l0; *(uint32_t*)(g_Vtl + gout + 2) = l1;
    }
}

// ---------------------------------------------------------------------------
// Flash attention on mma.sync, bf16 split-3. CTA = 128 q-rows x one (b,h).
// 8 warps, each one m16 tile. kv-tile = 64 keys, double-buffered cp.async.
// ---------------------------------------------------------------------------
#define FPITCH 72                // bf16 per smem row (144 B) -> conflict-free
#define FROWB  144
// dynamic smem offsets (bytes)
#define SQH   0
#define SQL   18432              // 128*144
#define SKV0  36864              // per buf: Kh,Kl,Vh,Vl each 64*144=9216
#define KVBUF 36864
#define OKH   0
#define OKL   9216
#define OVH   18432
#define OVL   27648
#define SMK   110592             // mask ints: 2 bufs x 64 x 4B
#define FSMEM 111104

__global__ __launch_bounds__(256, 1)
void flash_mma(const __nv_bfloat16* __restrict__ Qh, const __nv_bfloat16* __restrict__ Ql,
               const __nv_bfloat16* __restrict__ Kh, const __nv_bfloat16* __restrict__ Kl,
               const __nv_bfloat16* __restrict__ Vh, const __nv_bfloat16* __restrict__ Vl,
               const int* __restrict__ mask,
               __nv_bfloat16* __restrict__ Ch, __nv_bfloat16* __restrict__ Cl) {
    extern __shared__ char sm[];
    const float NEG = __int_as_float(0xff800000u);
    const int tid = threadIdx.x;
    const int wid = tid >> 5;
    const int lane = tid & 31;
    const int gid = lane >> 2;
    const int t = lane & 3;
    const int q0 = blockIdx.x * 128;
    const int h = blockIdx.y;
    const int b = blockIdx.z;
    const size_t bh = (size_t)b * NH_ + h;

    const __nv_bfloat16* Qhp = Qh + (bh * S_ + q0) * HD_;
    const __nv_bfloat16* Qlp = Ql + (bh * S_ + q0) * HD_;
    const __nv_bfloat16* Khp = Kh + bh * S_ * HD_;
    const __nv_bfloat16* Klp = Kl + bh * S_ * HD_;
    const __nv_bfloat16* Vhp = Vh + bh * HD_ * S_;
    const __nv_bfloat16* Vlp = Vl + bh * HD_ * S_;
    const int* mkp = mask + b * S_;

    const uint32_t sb = smem_u32(sm);

    // Load Q (128 x 64 bf16, hi+lo) into smem
    #pragma unroll
    for (int i = 0; i < 4; i++) {
        int idx = tid + i * 256;          // 1024 chunks
        int r = idx >> 3, c = idx & 7;
        cp16(sb + SQH + r * FROWB + c * 16, Qhp + (size_t)r * HD_ + c * 8);
        cp16(sb + SQL + r * FROWB + c * 16, Qlp + (size_t)r * HD_ + c * 8);
    }
    asm volatile("cp.async.commit_group;" ::: "memory");

    auto load_kv = [&](int tile, int buf) {
        const int kv0 = tile * 64;
        const uint32_t kb = sb + SKV0 + buf * KVBUF;
        #pragma unroll
        for (int i = 0; i < 2; i++) {
            int idx = tid + i * 256;      // 512 chunks
            int r = idx >> 3, c = idx & 7;
            uint32_t so = r * FROWB + c * 16;
            cp16(kb + OKH + so, Khp + (size_t)(kv0 + r) * HD_ + c * 8);
            cp16(kb + OKL + so, Klp + (size_t)(kv0 + r) * HD_ + c * 8);
            cp16(kb + OVH + so, Vhp + (size_t)r * S_ + kv0 + c * 8);
            cp16(kb + OVL + so, Vlp + (size_t)r * S_ + kv0 + c * 8);
        }
        if (tid < 64) cp4(sb + SMK + buf * 256 + tid * 4, mkp + kv0 + tid);
        asm volatile("cp.async.commit_group;" ::: "memory");
    };

    load_kv(0, 0);

    float m0 = NEG, m1 = NEG, l0 = 0.f, l1 = 0.f;
    float ctx[8][4];
    #pragma unroll
    for (int nt = 0; nt < 8; nt++)
        #pragma unroll
        for (int e = 0; e < 4; e++) ctx[nt][e] = 0.f;

    const int m0r = wid * 16;   // warp's m-tile base row

    for (int tile = 0; tile < 32; tile++) {
        const int buf = tile & 1;
        if (tile + 1 < 32) {
            load_kv(tile + 1, buf ^ 1);
            asm volatile("cp.async.wait_group 1;" ::: "memory");
        } else {
            asm volatile("cp.async.wait_group 0;" ::: "memory");
        }
        __syncthreads();

        const char* kb = sm + SKV0 + buf * KVBUF;
        const int* mk = (const int*)(sm + SMK + buf * 256);

        // --- S = QK^T (split-3) ---
        float sc[8][4];
        #pragma unroll
        for (int nt = 0; nt < 8; nt++)
            #pragma unroll
            for (int e = 0; e < 4; e++) sc[nt][e] = 0.f;

        #pragma unroll
        for (int ks = 0; ks < 4; ks++) {
            const int kcb = ks * 32 + 4 * t;    // byte offset of k element 2t
            uint32_t ah[4], al[4];
            {
                const char* qa = sm + SQH + (m0r + gid) * FROWB + kcb;
                const char* qb = sm + SQH + (m0r + gid + 8) * FROWB + kcb;
                ah[0] = *(const uint32_t*)qa;
                ah[1] = *(const uint32_t*)qb;
                ah[2] = *(const uint32_t*)(qa + 16);
                ah[3] = *(const uint32_t*)(qb + 16);
                const char* qc = sm + SQL + (m0r + gid) * FROWB + kcb;
                const char* qd = sm + SQL + (m0r + gid + 8) * FROWB + kcb;
                al[0] = *(const uint32_t*)qc;
                al[1] = *(const uint32_t*)qd;
                al[2] = *(const uint32_t*)(qc + 16);
                al[3] = *(const uint32_t*)(qd + 16);
            }
            #pragma unroll
            for (int nt = 0; nt < 8; nt++) {
                const char* kr = kb + (nt * 8 + gid) * FROWB + kcb;
                uint32_t bhf[2] = { *(const uint32_t*)(kr + OKH),
                                    *(const uint32_t*)(kr + OKH + 16) };
                uint32_t blf[2] = { *(const uint32_t*)(kr + OKL),
                                    *(const uint32_t*)(kr + OKL + 16) };
                mma16816(sc[nt], ah, bhf);
                mma16816(sc[nt], al, bhf);
                mma16816(sc[nt], ah, blf);
            }
        }

        // --- scale, clip, mask; tile row max ---
        float tm0 = NEG, tm1 = NEG;
        #pragma unroll
        for (int nt = 0; nt < 8; nt++) {
            int c0 = nt * 8 + 2 * t;
            int k0 = mk[c0], k1 = mk[c0 + 1];
            float v;
            v = fminf(fmaxf(sc[nt][0] * 0.125f, -10000.f), 10000.f);
            sc[nt][0] = k0 ? v : NEG;
            v = fminf(fmaxf(sc[nt][1] * 0.125f, -10000.f), 10000.f);
            sc[nt][1] = k1 ? v : NEG;
            v = fminf(fmaxf(sc[nt][2] * 0.125f, -10000.f), 10000.f);
            sc[nt][2] = k0 ? v : NEG;
            v = fminf(fmaxf(sc[nt][3] * 0.125f, -10000.f), 10000.f);
            sc[nt][3] = k1 ? v : NEG;
            tm0 = fmaxf(tm0, fmaxf(sc[nt][0], sc[nt][1]));
            tm1 = fmaxf(tm1, fmaxf(sc[nt][2], sc[nt][3]));
        }
        tm0 = fmaxf(tm0, __shfl_xor_sync(0xffffffffu, tm0, 1));
        tm0 = fmaxf(tm0, __shfl_xor_sync(0xffffffffu, tm0, 2));
        tm1 = fmaxf(tm1, __shfl_xor_sync(0xffffffffu, tm1, 1));
        tm1 = fmaxf(tm1, __shfl_xor_sync(0xffffffffu, tm1, 2));

        float mn0 = fmaxf(m0, tm0), mn1 = fmaxf(m1, tm1);
        float al0 = (mn0 == NEG) ? 1.f : __expf(m0 - mn0);
        float al1 = (mn1 == NEG) ? 1.f : __expf(m1 - mn1);

        // --- p = exp(s - m); row sums ---
        float rs0 = 0.f, rs1 = 0.f;
        #pragma unroll
        for (int nt = 0; nt < 8; nt++) {
            float p;
            p = (sc[nt][0] == NEG) ? 0.f : __expf(sc[nt][0] - mn0);
            sc[nt][0] = p; rs0 += p;
            p = (sc[nt][1] == NEG) ? 0.f : __expf(sc[nt][1] - mn0);
            sc[nt][1] = p; rs0 += p;
            p = (sc[nt][2] == NEG) ? 0.f : __expf(sc[nt][2] - mn1);
            sc[nt][2] = p; rs1 += p;
            p = (sc[nt][3] == NEG) ? 0.f : __expf(sc[nt][3] - mn1);
            sc[nt][3] = p; rs1 += p;
        }
        rs0 += __shfl_xor_sync(0xffffffffu, rs0, 1);
        rs0 += __shfl_xor_sync(0xffffffffu, rs0, 2);
        rs1 += __shfl_xor_sync(0xffffffffu, rs1, 1);
        rs1 += __shfl_xor_sync(0xffffffffu, rs1, 2);
        l0 = l0 * al0 + rs0;
        l1 = l1 * al1 + rs1;
        m0 = mn0; m1 = mn1;

        #pragma unroll
        for (int nt = 0; nt < 8; nt++) {
            ctx[nt][0] *= al0; ctx[nt][1] *= al0;
            ctx[nt][2] *= al1; ctx[nt][3] *= al1;
        }

        // --- ctx += P @ Vt (split-3) ---
        #pragma unroll
        for (int kk = 0; kk < 4; kk++) {
            uint32_t aph[4], apl[4];
            pack_split(sc[2 * kk][0],     sc[2 * kk][1],     aph[0], apl[0]);
            pack_split(sc[2 * kk][2],     sc[2 * kk][3],     aph[1], apl[1]);
            pack_split(sc[2 * kk + 1][0], sc[2 * kk + 1][1], aph[2], apl[2]);
            pack_split(sc[2 * kk + 1][2], sc[2 * kk + 1][3], aph[3], apl[3]);
            const int kcb = kk * 32 + 4 * t;   // key byte offset
            #pragma unroll
            for (int nt = 0; nt < 8; nt++) {
                const char* vr = kb + (nt * 8 + gid) * FROWB + kcb;
                uint32_t bvh[2] = { *(const uint32_t*)(vr + OVH),
                                    *(const uint32_t*)(vr + OVH + 16) };
                uint32_t bvl[2] = { *(const uint32_t*)(vr + OVL),
                                    *(const uint32_t*)(vr + OVL + 16) };
                mma16816(ctx[nt], aph, bvh);
                mma16816(ctx[nt], apl, bvh);
                mma16816(ctx[nt], aph, bvl);
            }
        }
        __syncthreads();
    }

    // Epilogue: normalize, split to bf16, store
    const float inv0 = 1.f / l0;
    const float inv1 = 1.f / l1;
    const int r0 = b * S_ + q0 + m0r + gid;
    #pragma unroll
    for (int nt = 0; nt < 8; nt++) {
        const int d0 = h * HD_ + nt * 8 + 2 * t;
        uint32_t hi, lo;
        pack_split(ctx[nt][0] * inv0, ctx[nt][1] * inv0, hi, lo);
        *(uint32_t*)(Ch + (size_t)r0 * H_ + d0) = hi;
        *(uint32_t*)(Cl + (size_t)r0 * H_ + d0) = lo;
        pack_split(ctx[nt][2] * inv1, ctx[nt][3] * inv1, hi, lo);
        *(uint32_t*)(Ch + (size_t)(r0 + 8) * H_ + d0) = hi;
        *(uint32_t*)(Cl + (size_t)(r0 + 8) * H_ + d0) = lo;
    }
}

// ---------------------------------------------------------------------------
// Split fp32 -> (bf16 hi, bf16 lo), vectorized by 4
// ---------------------------------------------------------------------------
__global__ void xsplit(const float* __restrict__ A, __nv_bfloat16* __restrict__ Ah,
                       __nv_bfloat16* __restrict__ Al, int n4) {
    int i = blockIdx.x * blockDim.x + threadIdx.x;
    if (i >= n4) return;
    float4 v = ((const float4*)A)[i];
    uint32_t h0, l0, h1, l1;
    pack_split(v.x, v.y, h0, l0);
    pack_split(v.z, v.w, h1, l1);
    ((uint32_t*)Ah)[2 * i + 0] = h0;
    ((uint32_t*)Ah)[2 * i + 1] = h1;
    ((uint32_t*)Al)[2 * i + 0] = l0;
    ((uint32_t*)Al)[2 * i + 1] = l1;
}

// ---------------------------------------------------------------------------
// Transpose + split weights: W[K,N] fp32 -> WhT/WlT[N,K] bf16
// ---------------------------------------------------------------------------
__global__ void wsplit_t(const float* __restrict__ W, __nv_bfloat16* __restrict__ WhT,
                         __nv_bfloat16* __restrict__ WlT) {
    __shared__ float tbuf[32][33];
    int n0 = blockIdx.x * 32, k0 = blockIdx.y * 32;
    int x = threadIdx.x, y0 = threadIdx.y;
    #pragma unroll
    for (int i = y0; i < 32; i += 8)
        tbuf[i][x] = W[(size_t)(k0 + i) * H_ + n0 + x];
    __syncthreads();
    #pragma unroll
    for (int i = y0; i < 32; i += 8) {
        float v = tbuf[x][i];
        __nv_bfloat16 h = __float2bfloat16(v);
        WhT[(size_t)(n0 + i) * H_ + k0 + x] = h;
        WlT[(size_t)(n0 + i) * H_ + k0 + x] = __float2bfloat16(v - __bfloat162float(h));
    }
}

// ---------------------------------------------------------------------------
// Launch
// ---------------------------------------------------------------------------
extern "C" void kernel_launch(void* const* d_in, const int* in_sizes, int n_in,
                              void* d_out, int out_size) {
    const float* X    = (const float*)d_in[0];
    const int*   mask = (const int*)d_in[1];
    const float* WQ   = (const float*)d_in[2];
    const float* WK   = (const float*)d_in[3];
    const float* WV   = (const float*)d_in[4];
    const float* WO   = (const float*)d_in[5];
    float* out = (float*)d_out;

    float *Qd, *Kd, *Vd;
    __nv_bfloat16 *Xh, *Xl, *Wh, *Wl;
    __nv_bfloat16 *Qah, *Qal, *Kah, *Kal, *Vth, *Vtl, *Chp, *Clp;
    cudaGetSymbolAddress((void**)&Qd, g_Q);
    cudaGetSymbolAddress((void**)&Kd, g_K);
    cudaGetSymbolAddress((void**)&Vd, g_V);
    cudaGetSymbolAddress((void**)&Xh, g_Xh);
    cudaGetSymbolAddress((void**)&Xl, g_Xl);
    cudaGetSymbolAddress((void**)&Wh, g_Wh);
    cudaGetSymbolAddress((void**)&Wl, g_Wl);
    cudaGetSymbolAddress((void**)&Qah, g_Qah);
    cudaGetSymbolAddress((void**)&Qal, g_Qal);
    cudaGetSymbolAddress((void**)&Kah, g_Kah);
    cudaGetSymbolAddress((void**)&Kal, g_Kal);
    cudaGetSymbolAddress((void**)&Vth, g_Vth);
    cudaGetSymbolAddress((void**)&Vtl, g_Vtl);
    cudaGetSymbolAddress((void**)&Chp, g_Ch);
    cudaGetSymbolAddress((void**)&Clp, g_Cl);

    cudaFuncSetAttribute(flash_mma, cudaFuncAttributeMaxDynamicSharedMemorySize, FSMEM);

    const size_t WSZ = (size_t)H_ * H_;

    // Prep: split X; transpose+split weights
    xsplit<<<(M_ * H_ / 4 + 255) / 256, 256>>>(X, Xh, Xl, M_ * H_ / 4);
    dim3 wgrd(32, 32), wblk(32, 8);
    wsplit_t<<<wgrd, wblk>>>(WQ, Wh + 0 * WSZ, Wl + 0 * WSZ);
    wsplit_t<<<wgrd, wblk>>>(WK, Wh + 1 * WSZ, Wl + 1 * WSZ);
    wsplit_t<<<wgrd, wblk>>>(WV, Wh + 2 * WSZ, Wl + 2 * WSZ);
    wsplit_t<<<wgrd, wblk>>>(WO, Wh + 3 * WSZ, Wl + 3 * WSZ);

    // Q/K/V projections (mma.sync bf16 split-3)
    dim3 ggrd(H_ / TN, M_ / TM);   // (8, 32)
    gemm_mma<<<ggrd, 256>>>(Xh, Xl, Wh + 0 * WSZ, Wl + 0 * WSZ, Qd);
    gemm_mma<<<ggrd, 256>>>(Xh, Xl, Wh + 1 * WSZ, Wl + 1 * WSZ, Kd);
    gemm_mma<<<ggrd, 256>>>(Xh, Xl, Wh + 2 * WSZ, Wl + 2 * WSZ, Vd);

    // Reshape/split Q,K,V for attention
    dim3 pgrd(S_ / 64, NH_, B_);
    attn_prep<<<pgrd, 256>>>(Qd, Kd, Vd);

    // Attention on tensor cores
    dim3 fgrd(S_ / 128, NH_, B_);
    flash_mma<<<fgrd, 256, FSMEM>>>(Qah, Qal, Kah, Kal, Vth, Vtl, mask, Chp, Clp);

    // Output projection (context already split bf16)
    gemm_mma<<<ggrd, 256>>>(Chp, Clp, Wh + 3 * WSZ, Wl + 3 * WSZ, out);
}

// round 5
// speedup vs baseline: 2.7007x; 1.1576x over previous
#include <cuda_runtime.h>
#include <cuda_bf16.h>
#include <cstdint>

// Problem constants
#define B_  2
#define S_  2048
#define H_  1024
#define NH_ 16
#define HD_ 64
#define M_  (B_*S_)   // 4096 rows for all projections

// ---------------------------------------------------------------------------
// Scratch (allocation-free: device globals)
// ---------------------------------------------------------------------------
__device__ float g_Q[(size_t)M_ * H_];
__device__ float g_K[(size_t)M_ * H_];
__device__ float g_V[(size_t)M_ * H_];
__device__ __nv_bfloat16 g_Xh[(size_t)M_ * H_];
__device__ __nv_bfloat16 g_Xl[(size_t)M_ * H_];
__device__ __nv_bfloat16 g_Wh[4][(size_t)H_ * H_];   // transposed [N,K] high
__device__ __nv_bfloat16 g_Wl[4][(size_t)H_ * H_];   // transposed [N,K] low
// Per-head attention operands (bf16 split)
__device__ __nv_bfloat16 g_Qah[(size_t)M_ * H_];     // [b,h,s,d]
__device__ __nv_bfloat16 g_Qal[(size_t)M_ * H_];
__device__ __nv_bfloat16 g_Kah[(size_t)M_ * H_];     // [b,h,s,d]
__device__ __nv_bfloat16 g_Kal[(size_t)M_ * H_];
__device__ __nv_bfloat16 g_Vth[(size_t)M_ * H_];     // [b,h,d,s] (transposed)
__device__ __nv_bfloat16 g_Vtl[(size_t)M_ * H_];
__device__ __nv_bfloat16 g_Ch[(size_t)M_ * H_];      // context split [s,H]
__device__ __nv_bfloat16 g_Cl[(size_t)M_ * H_];

// ---------------------------------------------------------------------------
// Helpers
// ---------------------------------------------------------------------------
__device__ __forceinline__ uint32_t smem_u32(const void* p) {
    uint32_t a;
    asm("{ .reg .u64 t; cvta.to.shared.u64 t, %1; cvt.u32.u64 %0, t; }"
        : "=r"(a) : "l"(p));
    return a;
}
__device__ __forceinline__ void cp16(uint32_t s, const void* g) {
    asm volatile("cp.async.cg.shared.global [%0], [%1], 16;" :: "r"(s), "l"(g));
}
__device__ __forceinline__ void cp4(uint32_t s, const void* g) {
    asm volatile("cp.async.ca.shared.global [%0], [%1], 4;" :: "r"(s), "l"(g));
}
__device__ __forceinline__ void cp_commit() {
    asm volatile("cp.async.commit_group;" ::: "memory");
}
__device__ __forceinline__ void mma16816(float* c, const uint32_t* a, const uint32_t* b) {
    asm volatile(
        "mma.sync.aligned.m16n8k16.row.col.f32.bf16.bf16.f32 "
        "{%0,%1,%2,%3}, {%4,%5,%6,%7}, {%8,%9}, {%0,%1,%2,%3};"
        : "+f"(c[0]), "+f"(c[1]), "+f"(c[2]), "+f"(c[3])
        : "r"(a[0]), "r"(a[1]), "r"(a[2]), "r"(a[3]), "r"(b[0]), "r"(b[1]));
}
// pack two fp32 -> (bf16x2 hi, bf16x2 lo)
__device__ __forceinline__ void pack_split(float f0, float f1, uint32_t& hi, uint32_t& lo) {
    __nv_bfloat162 hh = __floats2bfloat162_rn(f0, f1);
    float r0 = f0 - __bfloat162float(hh.x);
    float r1 = f1 - __bfloat162float(hh.y);
    __nv_bfloat162 ll = __floats2bfloat162_rn(r0, r1);
    hi = *(uint32_t*)&hh;
    lo = *(uint32_t*)&ll;
}

// ---------------------------------------------------------------------------
// bf16 split-3 GEMM via mma.sync.  C[M_,H_] = Ah@BhT^T + Al@BhT^T + Ah@BlT^T
// CTA tile 128x256, K-chunk 32 (all 4 split tiles resident per chunk),
// 3-stage cp.async, 8 warps (2x4), warp tile 64x64.
// ---------------------------------------------------------------------------
#define TM 128
#define TN 256
#define TK 32
#define PITCH 40                 // bf16 per smem row (80 B)
#define OAH 0
#define OAL 10240                // 128*80
#define OBH 20480
#define OBL 40960                // + 256*80
#define STG 61440
#define NSTAGE 3
#define GSMEM (STG * NSTAGE)     // 184320
#define NCH (H_ / TK)            // 32

__global__ __launch_bounds__(256, 1)
void gemm_mma(const __nv_bfloat16* __restrict__ Ah, const __nv_bfloat16* __restrict__ Al,
              const __nv_bfloat16* __restrict__ BhT, const __nv_bfloat16* __restrict__ BlT,
              float* __restrict__ C) {
    extern __shared__ char gsm[];
    const int tid = threadIdx.x;
    const int wid = tid >> 5;
    const int lane = tid & 31;
    const int gid = lane >> 2;
    const int t = lane & 3;
    const int wm = wid & 1;          // 2 warps in M
    const int wn = wid >> 1;         // 4 warps in N
    const int row0 = blockIdx.y * TM;
    const int col0 = blockIdx.x * TN;
    const uint32_t sb = smem_u32(gsm);

    float acc[4][8][4];
    #pragma unroll
    for (int i = 0; i < 4; i++)
        #pragma unroll
        for (int j = 0; j < 8; j++)
            #pragma unroll
            for (int q = 0; q < 4; q++) acc[i][j][q] = 0.f;

    auto load_chunk = [&](int c, int s) {
        const int k0 = c * TK;
        const uint32_t base = sb + s * STG;
        #pragma unroll
        for (int i = 0; i < 2; i++) {               // A: 512 chunks per array
            int idx = tid + i * 256;
            int r = idx >> 2, c16 = idx & 3;
            uint32_t so = r * 80 + c16 * 16;
            size_t g = (size_t)(row0 + r) * H_ + k0 + c16 * 8;
            cp16(base + OAH + so, Ah + g);
            cp16(base + OAL + so, Al + g);
        }
        #pragma unroll
        for (int i = 0; i < 4; i++) {               // B: 1024 chunks per array
            int idx = tid + i * 256;
            int r = idx >> 2, c16 = idx & 3;
            uint32_t so = r * 80 + c16 * 16;
            size_t g = (size_t)(col0 + r) * H_ + k0 + c16 * 8;
            cp16(base + OBH + so, BhT + g);
            cp16(base + OBL + so, BlT + g);
        }
        cp_commit();
    };

    load_chunk(0, 0);
    load_chunk(1, 1);

    for (int c = 0; c < NCH; c++) {
        const int s = c % NSTAGE;
        if (c + 2 < NCH) load_chunk(c + 2, (c + 2) % NSTAGE);
        else cp_commit();                           // keep group count uniform
        asm volatile("cp.async.wait_group 2;" ::: "memory");
        __syncthreads();

        const char* bs = gsm + s * STG;
        const __nv_bfloat16* Ahp = (const __nv_bfloat16*)(bs + OAH);
        const __nv_bfloat16* Alp = (const __nv_bfloat16*)(bs + OAL);
        const __nv_bfloat16* Bhp = (const __nv_bfloat16*)(bs + OBH);
        const __nv_bfloat16* Blp = (const __nv_bfloat16*)(bs + OBL);

        #pragma unroll
        for (int ks = 0; ks < 2; ks++) {
            const int kc = ks * 16 + 2 * t;
            uint32_t ah[4][4], al[4][4];
            #pragma unroll
            for (int mt = 0; mt < 4; mt++) {
                const int r0 = wm * 64 + mt * 16 + gid;
                ah[mt][0] = *(const uint32_t*)(Ahp + r0 * PITCH + kc);
                ah[mt][1] = *(const uint32_t*)(Ahp + (r0 + 8) * PITCH + kc);
                ah[mt][2] = *(const uint32_t*)(Ahp + r0 * PITCH + kc + 8);
                ah[mt][3] = *(const uint32_t*)(Ahp + (r0 + 8) * PITCH + kc + 8);
                al[mt][0] = *(const uint32_t*)(Alp + r0 * PITCH + kc);
                al[mt][1] = *(const uint32_t*)(Alp + (r0 + 8) * PITCH + kc);
                al[mt][2] = *(const uint32_t*)(Alp + r0 * PITCH + kc + 8);
                al[mt][3] = *(const uint32_t*)(Alp + (r0 + 8) * PITCH + kc + 8);
            }
            #pragma unroll
            for (int half = 0; half < 2; half++) {
                uint32_t bh[4][2], bl[4][2];
                #pragma unroll
                for (int n4 = 0; n4 < 4; n4++) {
                    const int n0 = wn * 64 + (half * 4 + n4) * 8 + gid;
                    bh[n4][0] = *(const uint32_t*)(Bhp + n0 * PITCH + kc);
                    bh[n4][1] = *(const uint32_t*)(Bhp + n0 * PITCH + kc + 8);
                    bl[n4][0] = *(const uint32_t*)(Blp + n0 * PITCH + kc);
                    bl[n4][1] = *(const uint32_t*)(Blp + n0 * PITCH + kc + 8);
                }
                #pragma unroll
                for (int mt = 0; mt < 4; mt++)
                    #pragma unroll
                    for (int n4 = 0; n4 < 4; n4++) {
                        float* a = acc[mt][half * 4 + n4];
                        mma16816(a, ah[mt], bh[n4]);
                        mma16816(a, al[mt], bh[n4]);
                        mma16816(a, ah[mt], bl[n4]);
                    }
            }
        }
        __syncthreads();
    }

    #pragma unroll
    for (int mt = 0; mt < 4; mt++) {
        const int rg = row0 + wm * 64 + mt * 16 + gid;
        #pragma unroll
        for (int nt = 0; nt < 8; nt++) {
            const int cg = col0 + wn * 64 + nt * 8 + 2 * t;
            *(float2*)(C + (size_t)rg * H_ + cg) =
                make_float2(acc[mt][nt][0], acc[mt][nt][1]);
            *(float2*)(C + (size_t)(rg + 8) * H_ + cg) =
                make_float2(acc[mt][nt][2], acc[mt][nt][3]);
        }
    }
}

// ---------------------------------------------------------------------------
// Prep: fp32 Q/K/V -> per-head split bf16 (Q,K straight; V transposed)
// ---------------------------------------------------------------------------
__global__ __launch_bounds__(256)
void attn_prep(const float* __restrict__ Qf, const float* __restrict__ Kf,
               const float* __restrict__ Vf) {
    __shared__ float vt[64][65];
    const int tid = threadIdx.x;
    const int s0 = blockIdx.x * 64;
    const int h = blockIdx.y;
    const int b = blockIdx.z;
    const size_t bh = (size_t)b * NH_ + h;

    #pragma unroll
    for (int i = 0; i < 4; i++) {
        int idx = tid + i * 256;
        int r = idx >> 4;
        int c4 = (idx & 15) * 4;
        size_t gin = (size_t)(b * S_ + s0 + r) * H_ + h * HD_ + c4;
        size_t gout = (bh * S_ + s0 + r) * HD_ + c4;

        float4 q = *(const float4*)(Qf + gin);
        uint32_t h0, l0, h1, l1;
        pack_split(q.x, q.y, h0, l0);
        pack_split(q.z, q.w, h1, l1);
        *(uint32_t*)(g_Qah + gout) = h0; *(uint32_t*)(g_Qah + gout + 2) = h1;
        *(uint32_t*)(g_Qal + gout) = l0; *(uint32_t*)(g_Qal + gout + 2) = l1;

        float4 k = *(const float4*)(Kf + gin);
        pack_split(k.x, k.y, h0, l0);
        pack_split(k.z, k.w, h1, l1);
        *(uint32_t*)(g_Kah + gout) = h0; *(uint32_t*)(g_Kah + gout + 2) = h1;
        *(uint32_t*)(g_Kal + gout) = l0; *(uint32_t*)(g_Kal + gout + 2) = l1;

        float4 v = *(const float4*)(Vf + gin);
        vt[r][c4 + 0] = v.x; vt[r][c4 + 1] = v.y;
        vt[r][c4 + 2] = v.z; vt[r][c4 + 3] = v.w;
    }
    __syncthreads();
    #pragma unroll
    for (int i = 0; i < 4; i++) {
        int idx = tid + i * 256;
        int d = idx >> 4;
        int s4 = (idx & 15) * 4;
        float f0 = vt[s4 + 0][d], f1 = vt[s4 + 1][d];
        float f2 = vt[s4 + 2][d], f3 = vt[s4 + 3][d];
        uint32_t h0, l0, h1, l1;
        pack_split(f0, f1, h0, l0);
        pack_split(f2, f3, h1, l1);
        size_t gout = (bh * HD_ + d) * S_ + s0 + s4;
        *(uint32_t*)(g_Vth + gout) = h0; *(uint32_t*)(g_Vth + gout + 2) = h1;
        *(uint32_t*)(g_Vtl + gout) = l0; *(uint32_t*)(g_Vtl + gout + 2) = l1;
    }
}

// ---------------------------------------------------------------------------
// Flash attention on mma.sync, bf16 split-3. CTA = 256 q-rows x one (b,h).
// 8 warps x 32 q-rows (two m16 tiles). kv-tile = 64 keys, double-buffered.
// ---------------------------------------------------------------------------
#define FROWB 144
#define SQH   0
#define SQL   36864              // 256*144
#define SKV0  73728
#define KVBUF 36864              // Kh,Kl,Vh,Vl each 64*144=9216
#define OKH   0
#define OKL   9216
#define OVH   18432
#define OVL   27648
#define SMK   147456             // mask ints: 2 bufs x 64 x 4B
#define FSMEM 147968

__global__ __launch_bounds__(256, 1)
void flash_mma(const __nv_bfloat16* __restrict__ Qh, const __nv_bfloat16* __restrict__ Ql,
               const __nv_bfloat16* __restrict__ Kh, const __nv_bfloat16* __restrict__ Kl,
               const __nv_bfloat16* __restrict__ Vh, const __nv_bfloat16* __restrict__ Vl,
               const int* __restrict__ mask,
               __nv_bfloat16* __restrict__ Ch, __nv_bfloat16* __restrict__ Cl) {
    extern __shared__ char sm[];
    const float NEG = __int_as_float(0xff800000u);
    const int tid = threadIdx.x;
    const int wid = tid >> 5;
    const int lane = tid & 31;
    const int gid = lane >> 2;
    const int t = lane & 3;
    const int q0 = blockIdx.x * 256;
    const int h = blockIdx.y;
    const int b = blockIdx.z;
    const size_t bh = (size_t)b * NH_ + h;

    const __nv_bfloat16* Qhp = Qh + (bh * S_ + q0) * HD_;
    const __nv_bfloat16* Qlp = Ql + (bh * S_ + q0) * HD_;
    const __nv_bfloat16* Khp = Kh + bh * S_ * HD_;
    const __nv_bfloat16* Klp = Kl + bh * S_ * HD_;
    const __nv_bfloat16* Vhp = Vh + bh * HD_ * S_;
    const __nv_bfloat16* Vlp = Vl + bh * HD_ * S_;
    const int* mkp = mask + b * S_;

    const uint32_t sb = smem_u32(sm);

    // Load Q (256 x 64 bf16, hi+lo)
    #pragma unroll
    for (int i = 0; i < 8; i++) {
        int idx = tid + i * 256;          // 2048 chunks per array
        int r = idx >> 3, c = idx & 7;
        cp16(sb + SQH + r * FROWB + c * 16, Qhp + (size_t)r * HD_ + c * 8);
        cp16(sb + SQL + r * FROWB + c * 16, Qlp + (size_t)r * HD_ + c * 8);
    }
    cp_commit();

    auto load_kv = [&](int tile, int buf) {
        const int kv0 = tile * 64;
        const uint32_t kb = sb + SKV0 + buf * KVBUF;
        #pragma unroll
        for (int i = 0; i < 2; i++) {
            int idx = tid + i * 256;
            int r = idx >> 3, c = idx & 7;
            uint32_t so = r * FROWB + c * 16;
            cp16(kb + OKH + so, Khp + (size_t)(kv0 + r) * HD_ + c * 8);
            cp16(kb + OKL + so, Klp + (size_t)(kv0 + r) * HD_ + c * 8);
            cp16(kb + OVH + so, Vhp + (size_t)r * S_ + kv0 + c * 8);
            cp16(kb + OVL + so, Vlp + (size_t)r * S_ + kv0 + c * 8);
        }
        if (tid < 64) cp4(sb + SMK + buf * 256 + tid * 4, mkp + kv0 + tid);
        cp_commit();
    };

    load_kv(0, 0);

    float mr[2][2], lr[2][2];
    #pragma unroll
    for (int mi = 0; mi < 2; mi++) {
        mr[mi][0] = NEG; mr[mi][1] = NEG;
        lr[mi][0] = 0.f; lr[mi][1] = 0.f;
    }
    float ctx[2][8][4];
    #pragma unroll
    for (int mi = 0; mi < 2; mi++)
        #pragma unroll
        for (int nt = 0; nt < 8; nt++)
            #pragma unroll
            for (int e = 0; e < 4; e++) ctx[mi][nt][e] = 0.f;

    const int m0r = wid * 32;

    for (int tile = 0; tile < 32; tile++) {
        const int buf = tile & 1;
        if (tile + 1 < 32) {
            load_kv(tile + 1, buf ^ 1);
            asm volatile("cp.async.wait_group 1;" ::: "memory");
        } else {
            asm volatile("cp.async.wait_group 0;" ::: "memory");
        }
        __syncthreads();

        const char* kb = sm + SKV0 + buf * KVBUF;
        const int* mk = (const int*)(sm + SMK + buf * 256);

        // --- S = QK^T (split-3), two m-tiles ---
        float sc[2][8][4];
        #pragma unroll
        for (int mi = 0; mi < 2; mi++)
            #pragma unroll
            for (int nt = 0; nt < 8; nt++)
                #pragma unroll
                for (int e = 0; e < 4; e++) sc[mi][nt][e] = 0.f;

        #pragma unroll
        for (int ks = 0; ks < 4; ks++) {
            const int kcb = ks * 32 + 4 * t;
            uint32_t ah[2][4], al[2][4];
            #pragma unroll
            for (int mi = 0; mi < 2; mi++) {
                const int r0 = m0r + mi * 16;
                const char* qa = sm + SQH + (r0 + gid) * FROWB + kcb;
                const char* qb = sm + SQH + (r0 + gid + 8) * FROWB + kcb;
                ah[mi][0] = *(const uint32_t*)qa;
                ah[mi][1] = *(const uint32_t*)qb;
                ah[mi][2] = *(const uint32_t*)(qa + 16);
                ah[mi][3] = *(const uint32_t*)(qb + 16);
                const char* qc = sm + SQL + (r0 + gid) * FROWB + kcb;
                const char* qd = sm + SQL + (r0 + gid + 8) * FROWB + kcb;
                al[mi][0] = *(const uint32_t*)qc;
                al[mi][1] = *(const uint32_t*)qd;
                al[mi][2] = *(const uint32_t*)(qc + 16);
                al[mi][3] = *(const uint32_t*)(qd + 16);
            }
            #pragma unroll
            for (int nt = 0; nt < 8; nt++) {
                const char* kr = kb + (nt * 8 + gid) * FROWB + kcb;
                uint32_t bhf[2] = { *(const uint32_t*)(kr + OKH),
                                    *(const uint32_t*)(kr + OKH + 16) };
                uint32_t blf[2] = { *(const uint32_t*)(kr + OKL),
                                    *(const uint32_t*)(kr + OKL + 16) };
                #pragma unroll
                for (int mi = 0; mi < 2; mi++) {
                    mma16816(sc[mi][nt], ah[mi], bhf);
                    mma16816(sc[mi][nt], al[mi], bhf);
                    mma16816(sc[mi][nt], ah[mi], blf);
                }
            }
        }

        // --- scale, clip, mask; online softmax (per m-tile) ---
        #pragma unroll
        for (int mi = 0; mi < 2; mi++) {
            float tm0 = NEG, tm1 = NEG;
            #pragma unroll
            for (int nt = 0; nt < 8; nt++) {
                int c0 = nt * 8 + 2 * t;
                int k0 = mk[c0], k1 = mk[c0 + 1];
                float v;
                v = fminf(fmaxf(sc[mi][nt][0] * 0.125f, -10000.f), 10000.f);
                sc[mi][nt][0] = k0 ? v : NEG;
                v = fminf(fmaxf(sc[mi][nt][1] * 0.125f, -10000.f), 10000.f);
                sc[mi][nt][1] = k1 ? v : NEG;
                v = fminf(fmaxf(sc[mi][nt][2] * 0.125f, -10000.f), 10000.f);
                sc[mi][nt][2] = k0 ? v : NEG;
                v = fminf(fmaxf(sc[mi][nt][3] * 0.125f, -10000.f), 10000.f);
                sc[mi][nt][3] = k1 ? v : NEG;
                tm0 = fmaxf(tm0, fmaxf(sc[mi][nt][0], sc[mi][nt][1]));
                tm1 = fmaxf(tm1, fmaxf(sc[mi][nt][2], sc[mi][nt][3]));
            }
            tm0 = fmaxf(tm0, __shfl_xor_sync(0xffffffffu, tm0, 1));
            tm0 = fmaxf(tm0, __shfl_xor_sync(0xffffffffu, tm0, 2));
            tm1 = fmaxf(tm1, __shfl_xor_sync(0xffffffffu, tm1, 1));
            tm1 = fmaxf(tm1, __shfl_xor_sync(0xffffffffu, tm1, 2));

            float mn0 = fmaxf(mr[mi][0], tm0), mn1 = fmaxf(mr[mi][1], tm1);
            float al0 = (mn0 == NEG) ? 1.f : __expf(mr[mi][0] - mn0);
            float al1 = (mn1 == NEG) ? 1.f : __expf(mr[mi][1] - mn1);

            float rs0 = 0.f, rs1 = 0.f;
            #pragma unroll
            for (int nt = 0; nt < 8; nt++) {
                float p;
                p = (sc[mi][nt][0] == NEG) ? 0.f : __expf(sc[mi][nt][0] - mn0);
                sc[mi][nt][0] = p; rs0 += p;
                p = (sc[mi][nt][1] == NEG) ? 0.f : __expf(sc[mi][nt][1] - mn0);
                sc[mi][nt][1] = p; rs0 += p;
                p = (sc[mi][nt][2] == NEG) ? 0.f : __expf(sc[mi][nt][2] - mn1);
                sc[mi][nt][2] = p; rs1 += p;
                p = (sc[mi][nt][3] == NEG) ? 0.f : __expf(sc[mi][nt][3] - mn1);
                sc[mi][nt][3] = p; rs1 += p;
            }
            rs0 += __shfl_xor_sync(0xffffffffu, rs0, 1);
            rs0 += __shfl_xor_sync(0xffffffffu, rs0, 2);
            rs1 += __shfl_xor_sync(0xffffffffu, rs1, 1);
            rs1 += __shfl_xor_sync(0xffffffffu, rs1, 2);
            lr[mi][0] = lr[mi][0] * al0 + rs0;
            lr[mi][1] = lr[mi][1] * al1 + rs1;
            mr[mi][0] = mn0; mr[mi][1] = mn1;

            #pragma unroll
            for (int nt = 0; nt < 8; nt++) {
                ctx[mi][nt][0] *= al0; ctx[mi][nt][1] *= al0;
                ctx[mi][nt][2] *= al1; ctx[mi][nt][3] *= al1;
            }
        }

        // --- ctx += P @ Vt (split-3) ---
        #pragma unroll
        for (int kk = 0; kk < 4; kk++) {
            uint32_t aph[2][4], apl[2][4];
            #pragma unroll
            for (int mi = 0; mi < 2; mi++) {
                pack_split(sc[mi][2 * kk][0],     sc[mi][2 * kk][1],     aph[mi][0], apl[mi][0]);
                pack_split(sc[mi][2 * kk][2],     sc[mi][2 * kk][3],     aph[mi][1], apl[mi][1]);
                pack_split(sc[mi][2 * kk + 1][0], sc[mi][2 * kk + 1][1], aph[mi][2], apl[mi][2]);
                pack_split(sc[mi][2 * kk + 1][2], sc[mi][2 * kk + 1][3], aph[mi][3], apl[mi][3]);
            }
            const int kcb = kk * 32 + 4 * t;
            #pragma unroll
            for (int nt = 0; nt < 8; nt++) {
                const char* vr = kb + (nt * 8 + gid) * FROWB + kcb;
                uint32_t bvh[2] = { *(const uint32_t*)(vr + OVH),
                                    *(const uint32_t*)(vr + OVH + 16) };
                uint32_t bvl[2] = { *(const uint32_t*)(vr + OVL),
                                    *(const uint32_t*)(vr + OVL + 16) };
                #pragma unroll
                for (int mi = 0; mi < 2; mi++) {
                    mma16816(ctx[mi][nt], aph[mi], bvh);
                    mma16816(ctx[mi][nt], apl[mi], bvh);
                    mma16816(ctx[mi][nt], aph[mi], bvl);
                }
            }
        }
        __syncthreads();
    }

    // Epilogue: normalize, split to bf16, store
    #pragma unroll
    for (int mi = 0; mi < 2; mi++) {
        const float inv0 = 1.f / lr[mi][0];
        const float inv1 = 1.f / lr[mi][1];
        const int r0 = b * S_ + q0 + m0r + mi * 16 + gid;
        #pragma unroll
        for (int nt = 0; nt < 8; nt++) {
            const int d0 = h * HD_ + nt * 8 + 2 * t;
            uint32_t hi, lo;
            pack_split(ctx[mi][nt][0] * inv0, ctx[mi][nt][1] * inv0, hi, lo);
            *(uint32_t*)(Ch + (size_t)r0 * H_ + d0) = hi;
            *(uint32_t*)(Cl + (size_t)r0 * H_ + d0) = lo;
            pack_split(ctx[mi][nt][2] * inv1, ctx[mi][nt][3] * inv1, hi, lo);
            *(uint32_t*)(Ch + (size_t)(r0 + 8) * H_ + d0) = hi;
            *(uint32_t*)(Cl + (size_t)(r0 + 8) * H_ + d0) = lo;
        }
    }
}

// ---------------------------------------------------------------------------
// Split fp32 -> (bf16 hi, bf16 lo), vectorized by 4
// ---------------------------------------------------------------------------
__global__ void xsplit(const float* __restrict__ A, __nv_bfloat16* __restrict__ Ah,
                       __nv_bfloat16* __restrict__ Al, int n4) {
    int i = blockIdx.x * blockDim.x + threadIdx.x;
    if (i >= n4) return;
    float4 v = ((const float4*)A)[i];
    uint32_t h0, l0, h1, l1;
    pack_split(v.x, v.y, h0, l0);
    pack_split(v.z, v.w, h1, l1);
    ((uint32_t*)Ah)[2 * i + 0] = h0;
    ((uint32_t*)Ah)[2 * i + 1] = h1;
    ((uint32_t*)Al)[2 * i + 0] = l0;
    ((uint32_t*)Al)[2 * i + 1] = l1;
}

// ---------------------------------------------------------------------------
// Transpose + split weights: W[K,N] fp32 -> WhT/WlT[N,K] bf16
// ---------------------------------------------------------------------------
__global__ void wsplit_t(const float* __restrict__ W, __nv_bfloat16* __restrict__ WhT,
                         __nv_bfloat16* __restrict__ WlT) {
    __shared__ float tbuf[32][33];
    int n0 = blockIdx.x * 32, k0 = blockIdx.y * 32;
    int x = threadIdx.x, y0 = threadIdx.y;
    #pragma unroll
    for (int i = y0; i < 32; i += 8)
        tbuf[i][x] = W[(size_t)(k0 + i) * H_ + n0 + x];
    __syncthreads();
    #pragma unroll
    for (int i = y0; i < 32; i += 8) {
        float v = tbuf[x][i];
        __nv_bfloat16 hh = __float2bfloat16(v);
        WhT[(size_t)(n0 + i) * H_ + k0 + x] = hh;
        WlT[(size_t)(n0 + i) * H_ + k0 + x] = __float2bfloat16(v - __bfloat162float(hh));
    }
}

// ---------------------------------------------------------------------------
// Launch
// ---------------------------------------------------------------------------
extern "C" void kernel_launch(void* const* d_in, const int* in_sizes, int n_in,
                              void* d_out, int out_size) {
    const float* X    = (const float*)d_in[0];
    const int*   mask = (const int*)d_in[1];
    const float* WQ   = (const float*)d_in[2];
    const float* WK   = (const float*)d_in[3];
    const float* WV   = (const float*)d_in[4];
    const float* WO   = (const float*)d_in[5];
    float* out = (float*)d_out;

    float *Qd, *Kd, *Vd;
    __nv_bfloat16 *Xh, *Xl, *Wh, *Wl;
    __nv_bfloat16 *Qah, *Qal, *Kah, *Kal, *Vth, *Vtl, *Chp, *Clp;
    cudaGetSymbolAddress((void**)&Qd, g_Q);
    cudaGetSymbolAddress((void**)&Kd, g_K);
    cudaGetSymbolAddress((void**)&Vd, g_V);
    cudaGetSymbolAddress((void**)&Xh, g_Xh);
    cudaGetSymbolAddress((void**)&Xl, g_Xl);
    cudaGetSymbolAddress((void**)&Wh, g_Wh);
    cudaGetSymbolAddress((void**)&Wl, g_Wl);
    cudaGetSymbolAddress((void**)&Qah, g_Qah);
    cudaGetSymbolAddress((void**)&Qal, g_Qal);
    cudaGetSymbolAddress((void**)&Kah, g_Kah);
    cudaGetSymbolAddress((void**)&Kal, g_Kal);
    cudaGetSymbolAddress((void**)&Vth, g_Vth);
    cudaGetSymbolAddress((void**)&Vtl, g_Vtl);
    cudaGetSymbolAddress((void**)&Chp, g_Ch);
    cudaGetSymbolAddress((void**)&Clp, g_Cl);

    cudaFuncSetAttribute(gemm_mma, cudaFuncAttributeMaxDynamicSharedMemorySize, GSMEM);
    cudaFuncSetAttribute(flash_mma, cudaFuncAttributeMaxDynamicSharedMemorySize, FSMEM);

    const size_t WSZ = (size_t)H_ * H_;

    // Prep: split X; transpose+split weights
    xsplit<<<(M_ * H_ / 4 + 255) / 256, 256>>>(X, Xh, Xl, M_ * H_ / 4);
    dim3 wgrd(32, 32), wblk(32, 8);
    wsplit_t<<<wgrd, wblk>>>(WQ, Wh + 0 * WSZ, Wl + 0 * WSZ);
    wsplit_t<<<wgrd, wblk>>>(WK, Wh + 1 * WSZ, Wl + 1 * WSZ);
    wsplit_t<<<wgrd, wblk>>>(WV, Wh + 2 * WSZ, Wl + 2 * WSZ);
    wsplit_t<<<wgrd, wblk>>>(WO, Wh + 3 * WSZ, Wl + 3 * WSZ);

    // Q/K/V projections (mma.sync bf16 split-3, 128x256 tiles, 3-stage)
    dim3 ggrd(H_ / TN, M_ / TM);   // (4, 32)
    gemm_mma<<<ggrd, 256, GSMEM>>>(Xh, Xl, Wh + 0 * WSZ, Wl + 0 * WSZ, Qd);
    gemm_mma<<<ggrd, 256, GSMEM>>>(Xh, Xl, Wh + 1 * WSZ, Wl + 1 * WSZ, Kd);
    gemm_mma<<<ggrd, 256, GSMEM>>>(Xh, Xl, Wh + 2 * WSZ, Wl + 2 * WSZ, Vd);

    // Reshape/split Q,K,V for attention
    dim3 pgrd(S_ / 64, NH_, B_);
    attn_prep<<<pgrd, 256>>>(Qd, Kd, Vd);

    // Attention on tensor cores (256 q-rows per CTA)
    dim3 fgrd(S_ / 256, NH_, B_);
    flash_mma<<<fgrd, 256, FSMEM>>>(Qah, Qal, Kah, Kal, Vth, Vtl, mask, Chp, Clp);

    // Output projection (context already split bf16)
    gemm_mma<<<ggrd, 256, GSMEM>>>(Chp, Clp, Wh + 3 * WSZ, Wl + 3 * WSZ, out);
}